// round 8
// baseline (speedup 1.0000x reference)
#include <cuda_runtime.h>
#include <cstdint>
#include <cstddef>

// Problem dims
#define BB    64
#define CC    512
#define HWS   784
#define MTOT  (BB * HWS)        // 50176
#define MTILE 128
#define NTILE 128
#define KCH   128               // K chunk (s8 -> 128B rows)
#define NCHNK (CC / KCH)        // 4

// smem: 2 stages x { A[128][128B] 16384 + B[128][128B] 16384 } = 65536
// epilogue D tile 128 x 129 f32 = 66048 (reuses stages, extends past them)
// params at 66048: 5 x 128 f32 = 2560 -> total 68608   (2 CTAs/SM)
#define STAGEB   32768u
#define SMPAR    66048u
#define SMTOTAL  68608u
#define TPITCH   129

// ---------------- scratch ----------------
__device__ char g_a[(size_t)MTOT * CC];    // binarized activations [M][K], +-1 s8
__device__ char g_wb[CC * CC];             // sign(W) [N][K], +-1 s8
__device__ float g_alpha[CC];
__device__ float g_beta2[CC];

// ---------------- helpers ----------------
static __device__ __forceinline__ uint32_t smem_u32(const void* p) {
    uint32_t a;
    asm("{ .reg .u64 t; cvta.to.shared.u64 t, %1; cvt.u32.u64 %0, t; }" : "=r"(a) : "l"(p));
    return a;
}
static __device__ __forceinline__ void cp16(uint32_t s, const void* g) {
    asm volatile("cp.async.cg.shared.global [%0], [%1], 16;" :: "r"(s), "l"(g) : "memory");
}
#define CP_COMMIT() asm volatile("cp.async.commit_group;" ::: "memory")
#define CP_WAIT(n)  asm volatile("cp.async.wait_group %0;" :: "n"(n) : "memory")

static __device__ __forceinline__ void ldsm4(uint32_t* r, uint32_t a) {
    asm volatile("ldmatrix.sync.aligned.m8n8.x4.shared.b16 {%0,%1,%2,%3}, [%4];"
                 : "=r"(r[0]), "=r"(r[1]), "=r"(r[2]), "=r"(r[3]) : "r"(a));
}
static __device__ __forceinline__ void mma_s8(int* c, const uint32_t* a,
                                              uint32_t b0, uint32_t b1) {
    asm volatile(
        "mma.sync.aligned.m16n8k32.row.col.s32.s8.s8.s32 "
        "{%0,%1,%2,%3}, {%4,%5,%6,%7}, {%8,%9}, {%0,%1,%2,%3};"
        : "+r"(c[0]), "+r"(c[1]), "+r"(c[2]), "+r"(c[3])
        : "r"(a[0]), "r"(a[1]), "r"(a[2]), "r"(a[3]), "r"(b0), "r"(b1));
}
// 128B-row swizzle
static __device__ __forceinline__ uint32_t swzB(int row, int seg) {
    return (uint32_t)(row * 128 + ((seg ^ (row & 7)) << 4));
}
static __device__ __forceinline__ uint32_t sgn4(float a, float b, float c, float d) {
    return (a >= 0.f ? 0x01u : 0xFFu)        | ((b >= 0.f ? 0x01u : 0xFFu) << 8) |
           ((c >= 0.f ? 0x01u : 0xFFu) << 16) | ((d >= 0.f ? 0x01u : 0xFFu) << 24);
}

// ---------------- kernel 1: epilogue constants + sign(W) in one pass ----------------
__global__ void prep_kernel(const float* __restrict__ W, const float* __restrict__ gam,
                            const float* __restrict__ bet, const float* __restrict__ mea,
                            const float* __restrict__ var) {
    int wid = threadIdx.x >> 5, lane = threadIdx.x & 31;
    int o = blockIdx.x * 8 + wid;
    const float4* wr = reinterpret_cast<const float4*>(W + (size_t)o * CC + lane * 16);
    float s = 0.f;
    uint32_t pk[4];
    #pragma unroll
    for (int j = 0; j < 4; j++) {
        float4 v = wr[j];
        s += fabsf(v.x) + fabsf(v.y) + fabsf(v.z) + fabsf(v.w);
        pk[j] = sgn4(v.x, v.y, v.z, v.w);
    }
    *reinterpret_cast<uint4*>(g_wb + (size_t)o * CC + lane * 16) =
        make_uint4(pk[0], pk[1], pk[2], pk[3]);
    #pragma unroll
    for (int off = 16; off > 0; off >>= 1) s += __shfl_xor_sync(0xffffffffu, s, off);
    if (lane == 0) {
        float scale = s * (1.0f / 512.0f);
        float A = gam[o] * rsqrtf(var[o] + 1e-5f);
        g_alpha[o] = A * scale;
        g_beta2[o] = bet[o] - A * mea[o];
    }
}

// ---------------- kernel 2: binarize x + transpose NCHW -> [M][K] s8 ----------------
__global__ void binarize_kernel(const float* __restrict__ x, const float* __restrict__ rb) {
    __shared__ char ts[64][80];             // [hw][c], pitch 80 (16B aligned rows)
    const int b   = blockIdx.z;
    const int k0  = blockIdx.y * 64;
    const int hw0 = blockIdx.x * 64;
    const int tid = threadIdx.x;

    #pragma unroll
    for (int i = 0; i < 4; i++) {
        int idx = tid + i * 256;            // 1024 tasks
        int cc = idx >> 4;                  // 0..63
        int hs = idx & 15;                  // float4 seg over hw
        int hw = hw0 + hs * 4;
        float rbv = rb[k0 + cc];
        const float* xp = x + (size_t)((b << 9) + k0 + cc) * HWS + hw;
        if (hw + 3 < HWS) {
            float4 v = *reinterpret_cast<const float4*>(xp);
            ts[hs * 4 + 0][cc] = (v.x + rbv >= 0.f) ? 1 : -1;
            ts[hs * 4 + 1][cc] = (v.y + rbv >= 0.f) ? 1 : -1;
            ts[hs * 4 + 2][cc] = (v.z + rbv >= 0.f) ? 1 : -1;
            ts[hs * 4 + 3][cc] = (v.w + rbv >= 0.f) ? 1 : -1;
        } else {
            #pragma unroll
            for (int e = 0; e < 4; e++)
                if (hw + e < HWS)
                    ts[hs * 4 + e][cc] = (xp[e] + rbv >= 0.f) ? 1 : -1;
        }
    }
    __syncthreads();
    {
        int row = tid >> 2;                 // 0..63
        int seg = tid & 3;                  // 16B seg
        int hw = hw0 + row;
        if (hw < HWS) {
            uint4 v = *reinterpret_cast<const uint4*>(&ts[row][seg * 16]);
            *reinterpret_cast<uint4*>(
                &g_a[(size_t)(b * HWS + hw) * CC + k0 + seg * 16]) = v;
        }
    }
}

// ---------------- kernel 3: s8 mma GEMM + fused BN/residual/RPReLU ----------------
__global__ void __launch_bounds__(256, 2)
gemm_kernel(const float* __restrict__ x, const float* __restrict__ slope,
            const float* __restrict__ shift, const float* __restrict__ pbias,
            float* __restrict__ out)
{
    extern __shared__ char smem[];
    const uint32_t sb = smem_u32(smem);
    const int tid = threadIdx.x, wid = tid >> 5, lane = tid & 31;
    const int m0 = blockIdx.y * MTILE;
    const int n0 = blockIdx.x * NTILE;

    float* alphaS = reinterpret_cast<float*>(smem + SMPAR);
    float* betaS  = alphaS + 128;
    float* slopeS = alphaS + 256;
    float* shiftS = alphaS + 384;
    float* pbiasS = alphaS + 512;
    if (tid < 128) {
        alphaS[tid] = g_alpha[n0 + tid];
        betaS[tid]  = g_beta2[n0 + tid];
        slopeS[tid] = slope[n0 + tid];
        shiftS[tid] = shift[n0 + tid];
        pbiasS[tid] = pbias[n0 + tid];
    }

    const int ldrow = tid >> 3;           // 0..31
    const int ldseg = tid & 7;            // 16B seg within 128B row
    auto load_stage = [&](int c, int st) {
        const uint32_t so = sb + (uint32_t)st * STAGEB;
        const char* ga = g_a  + (size_t)m0 * CC + c * KCH;
        const char* gb = g_wb + (size_t)n0 * CC + c * KCH;
        #pragma unroll
        for (int j = 0; j < 4; j++) {
            int row = ldrow + j * 32;
            cp16(so + swzB(row, ldseg), ga + (size_t)row * CC + ldseg * 16);
        }
        #pragma unroll
        for (int j = 0; j < 4; j++) {
            int row = ldrow + j * 32;
            cp16(so + 16384u + swzB(row, ldseg), gb + (size_t)row * CC + ldseg * 16);
        }
        CP_COMMIT();
    };

    load_stage(0, 0);

    int acc[4][4][4] = {};                // warp 64m x 32n, s32 acc
    const int mw = (wid >> 2) * 64;       // warp row: 0/64
    const int nw = (wid & 3) * 32;        // warp col: 0/32/64/96
    const int rowSel = (lane & 7) + ((lane >> 3) & 1) * 8;
    const int segHi  = (lane >> 4) & 1;

    #pragma unroll
    for (int c = 0; c < NCHNK; c++) {
        if (c + 1 < NCHNK) { load_stage(c + 1, (c + 1) & 1); CP_WAIT(1); }
        else               { CP_WAIT(0); }
        __syncthreads();

        const uint32_t aBase = sb + (uint32_t)(c & 1) * STAGEB;
        const uint32_t bBase = aBase + 16384u;
        #pragma unroll
        for (int ks = 0; ks < 4; ks++) {           // k32 steps within 128-k chunk
            uint32_t af[4][4], bf[2][4];
            #pragma unroll
            for (int mt = 0; mt < 4; mt++)
                ldsm4(af[mt], aBase + swzB(mw + mt * 16 + rowSel, ks * 2 + segHi));
            #pragma unroll
            for (int nb = 0; nb < 2; nb++)
                ldsm4(bf[nb], bBase + swzB(nw + nb * 16 + rowSel, ks * 2 + segHi));
            #pragma unroll
            for (int mt = 0; mt < 4; mt++) {
                #pragma unroll
                for (int nt = 0; nt < 4; nt++)
                    mma_s8(acc[mt][nt], af[mt], bf[nt >> 1][nt & 1], bf[nt >> 1][(nt & 1) + 2]);
            }
        }
        __syncthreads();
    }

    // ---- stage D through smem (exact int -> float) ----
    float* tile = reinterpret_cast<float*>(smem);
    const int dr = lane >> 2;
    const int dc = (lane & 3) * 2;
    #pragma unroll
    for (int mt = 0; mt < 4; mt++) {
        #pragma unroll
        for (int nt = 0; nt < 4; nt++) {
            int r = mw + mt * 16 + dr;
            int c2 = nw + nt * 8 + dc;
            tile[r * TPITCH + c2]           = (float)acc[mt][nt][0];
            tile[r * TPITCH + c2 + 1]       = (float)acc[mt][nt][1];
            tile[(r + 8) * TPITCH + c2]     = (float)acc[mt][nt][2];
            tile[(r + 8) * TPITCH + c2 + 1] = (float)acc[mt][nt][3];
        }
    }
    __syncthreads();

    // ---- epilogue: BN + residual + RPReLU, coalesced over hw ----
    #pragma unroll 4
    for (int g = 0; g < 16; g++) {
        const int nl = wid + 8 * g;
        const int n = n0 + nl;
        const float al = alphaS[nl], be = betaS[nl];
        const float sl = slopeS[nl], sh = shiftS[nl], pb = pbiasS[nl];
        #pragma unroll
        for (int j = 0; j < 4; j++) {
            int ml = lane + 32 * j;
            int m = m0 + ml;
            int b = m / HWS;
            int hw = m - b * HWS;
            size_t gi = ((size_t)(b * CC + n)) * HWS + hw;
            float raw = tile[ml * TPITCH + nl];
            float sv = fmaf(al, raw, be) + x[gi];
            float t = sv - sh;
            out[gi] = ((t > 0.f) ? t : sl * t) + pb;
        }
    }
}

// ---------------- launch ----------------
extern "C" void kernel_launch(void* const* d_in, const int* in_sizes, int n_in,
                              void* d_out, int out_size) {
    const float* x   = (const float*)d_in[0];
    const float* rb  = (const float*)d_in[1];
    const float* W   = (const float*)d_in[2];
    const float* gam = (const float*)d_in[3];
    const float* bet = (const float*)d_in[4];
    const float* mea = (const float*)d_in[5];
    const float* var = (const float*)d_in[6];
    const float* slo = (const float*)d_in[7];
    const float* shi = (const float*)d_in[8];
    const float* pbi = (const float*)d_in[9];
    float* out = (float*)d_out;

    cudaFuncSetAttribute(gemm_kernel, cudaFuncAttributeMaxDynamicSharedMemorySize, SMTOTAL);

    prep_kernel<<<64, 256>>>(W, gam, bet, mea, var);
    binarize_kernel<<<dim3(13, 8, 64), 256>>>(x, rb);
    gemm_kernel<<<dim3(4, MTOT / MTILE), 256, SMTOTAL>>>(x, slo, shi, pbi, out);
}

// round 9
// speedup vs baseline: 1.7971x; 1.7971x over previous
#include <cuda_runtime.h>
#include <cuda_fp16.h>
#include <cstdint>
#include <cstddef>

// Problem dims
#define BB    64
#define CC    512
#define HWS   784
#define MTOT  (BB * HWS)        // 50176
#define MTILE 128
#define NTILE 128
#define KCH   64                // K chunk (fp16 -> 128B rows)
#define NCHNK (CC / KCH)        // 8

// smem: 3 stages x { A[128][128B] 16384 + B[128][128B] 16384 } = 98304
// params at 98304: 5 x 128 f32 = 2560 -> total 100864  (2 CTAs/SM)
// epilogue D tile 128 x 129 f32 = 66048 reuses stage area
#define ASZ      16384u
#define STAGEB   32768u
#define SMPAR    98304u
#define SMTOTAL  100864u
#define TPITCH   129

// ---------------- scratch ----------------
__device__ __half g_a[(size_t)MTOT * CC];   // binarized activations [M][K], +-1 fp16
__device__ __half g_wb[CC * CC];            // sign(W) [N][K], +-1 fp16
__device__ float g_alpha[CC];
__device__ float g_beta2[CC];

// ---------------- helpers ----------------
static __device__ __forceinline__ uint32_t smem_u32(const void* p) {
    uint32_t a;
    asm("{ .reg .u64 t; cvta.to.shared.u64 t, %1; cvt.u32.u64 %0, t; }" : "=r"(a) : "l"(p));
    return a;
}
static __device__ __forceinline__ void cp16(uint32_t s, const void* g) {
    asm volatile("cp.async.cg.shared.global [%0], [%1], 16;" :: "r"(s), "l"(g) : "memory");
}
#define CP_COMMIT() asm volatile("cp.async.commit_group;" ::: "memory")
#define CP_WAIT(n)  asm volatile("cp.async.wait_group %0;" :: "n"(n) : "memory")

static __device__ __forceinline__ void ldsm4(uint32_t* r, uint32_t a) {
    asm volatile("ldmatrix.sync.aligned.m8n8.x4.shared.b16 {%0,%1,%2,%3}, [%4];"
                 : "=r"(r[0]), "=r"(r[1]), "=r"(r[2]), "=r"(r[3]) : "r"(a));
}
static __device__ __forceinline__ void mma_h(uint32_t* c, const uint32_t* a,
                                             uint32_t b0, uint32_t b1) {
    asm volatile(
        "mma.sync.aligned.m16n8k16.row.col.f16.f16.f16.f16 "
        "{%0,%1}, {%2,%3,%4,%5}, {%6,%7}, {%0,%1};"
        : "+r"(c[0]), "+r"(c[1])
        : "r"(a[0]), "r"(a[1]), "r"(a[2]), "r"(a[3]), "r"(b0), "r"(b1));
}
static __device__ __forceinline__ uint32_t swzB(int row, int seg) {
    return (uint32_t)(row * 128 + ((seg ^ (row & 7)) << 4));
}
static __device__ __forceinline__ uint32_t sgnh2(float a, float b) {
    return ((a >= 0.f) ? 0x3C00u : 0xBC00u) | (((b >= 0.f) ? 0x3C00u : 0xBC00u) << 16);
}

// ---------------- kernel 1: epilogue constants + sign(W) fp16, one pass ----------------
__global__ void prep_kernel(const float* __restrict__ W, const float* __restrict__ gam,
                            const float* __restrict__ bet, const float* __restrict__ mea,
                            const float* __restrict__ var) {
    int wid = threadIdx.x >> 5, lane = threadIdx.x & 31;
    int o = blockIdx.x * 8 + wid;
    const float4* wr = reinterpret_cast<const float4*>(W + (size_t)o * CC + lane * 16);
    float s = 0.f;
    uint32_t h[8];
    #pragma unroll
    for (int j = 0; j < 4; j++) {
        float4 v = wr[j];
        s += fabsf(v.x) + fabsf(v.y) + fabsf(v.z) + fabsf(v.w);
        h[2 * j]     = sgnh2(v.x, v.y);
        h[2 * j + 1] = sgnh2(v.z, v.w);
    }
    uint4* dst = reinterpret_cast<uint4*>(g_wb + (size_t)o * CC + lane * 16);
    dst[0] = make_uint4(h[0], h[1], h[2], h[3]);
    dst[1] = make_uint4(h[4], h[5], h[6], h[7]);
    #pragma unroll
    for (int off = 16; off > 0; off >>= 1) s += __shfl_xor_sync(0xffffffffu, s, off);
    if (lane == 0) {
        float scale = s * (1.0f / 512.0f);
        float A = gam[o] * rsqrtf(var[o] + 1e-5f);
        g_alpha[o] = A * scale;
        g_beta2[o] = bet[o] - A * mea[o];
    }
}

// ---------------- kernel 2: binarize x + transpose NCHW -> [M][K] fp16 ----------------
__global__ void binarize_kernel(const float* __restrict__ x, const float* __restrict__ rb) {
    __shared__ unsigned short ts[64][72];   // [hw][c]
    const int b   = blockIdx.z;
    const int k0  = blockIdx.y * 64;
    const int hw0 = blockIdx.x * 64;
    const int tid = threadIdx.x;

    #pragma unroll
    for (int i = 0; i < 4; i++) {
        int idx = tid + i * 256;
        int cc = idx >> 4;
        int hs = idx & 15;
        int hw = hw0 + hs * 4;
        float rbv = rb[k0 + cc];
        const float* xp = x + (size_t)((b << 9) + k0 + cc) * HWS + hw;
        if (hw + 3 < HWS) {
            float4 v = *reinterpret_cast<const float4*>(xp);
            ts[hs * 4 + 0][cc] = (v.x + rbv >= 0.f) ? 0x3C00 : 0xBC00;
            ts[hs * 4 + 1][cc] = (v.y + rbv >= 0.f) ? 0x3C00 : 0xBC00;
            ts[hs * 4 + 2][cc] = (v.z + rbv >= 0.f) ? 0x3C00 : 0xBC00;
            ts[hs * 4 + 3][cc] = (v.w + rbv >= 0.f) ? 0x3C00 : 0xBC00;
        } else {
            #pragma unroll
            for (int e = 0; e < 4; e++)
                if (hw + e < HWS)
                    ts[hs * 4 + e][cc] = (xp[e] + rbv >= 0.f) ? 0x3C00 : 0xBC00;
        }
    }
    __syncthreads();
    #pragma unroll
    for (int i = 0; i < 2; i++) {
        int idx = tid + i * 256;
        int row = idx >> 3;
        int seg = idx & 7;
        int hw = hw0 + row;
        if (hw < HWS) {
            uint4 v = *reinterpret_cast<const uint4*>(&ts[row][seg * 8]);
            *reinterpret_cast<uint4*>(
                &g_a[(size_t)(b * HWS + hw) * CC + k0 + seg * 8]) = v;
        }
    }
}

// ---------------- kernel 3: fp16 mma GEMM (3-stage, frag double-buffer) ----------------
__global__ void __launch_bounds__(256, 2)
gemm_kernel(const float* __restrict__ x, const float* __restrict__ slope,
            const float* __restrict__ shift, const float* __restrict__ pbias,
            float* __restrict__ out)
{
    extern __shared__ char smem[];
    const uint32_t sb = smem_u32(smem);
    const int tid = threadIdx.x, wid = tid >> 5, lane = tid & 31;
    const int m0 = blockIdx.y * MTILE;
    const int n0 = blockIdx.x * NTILE;

    float* alphaS = reinterpret_cast<float*>(smem + SMPAR);
    float* betaS  = alphaS + 128;
    float* slopeS = alphaS + 256;
    float* shiftS = alphaS + 384;
    float* pbiasS = alphaS + 512;
    if (tid < 128) {
        alphaS[tid] = g_alpha[n0 + tid];
        betaS[tid]  = g_beta2[n0 + tid];
        slopeS[tid] = slope[n0 + tid];
        shiftS[tid] = shift[n0 + tid];
        pbiasS[tid] = pbias[n0 + tid];
    }

    const int ldrow = tid >> 3;           // 0..31
    const int ldseg = tid & 7;
    auto load_stage = [&](int c, int st) {
        const uint32_t so = sb + (uint32_t)st * STAGEB;
        const char* ga = (const char*)g_a  + ((size_t)m0 * CC + c * KCH) * 2;
        const char* gb = (const char*)g_wb + ((size_t)n0 * CC + c * KCH) * 2;
        #pragma unroll
        for (int j = 0; j < 4; j++) {
            int row = ldrow + j * 32;
            cp16(so + swzB(row, ldseg), ga + (size_t)row * (CC * 2) + ldseg * 16);
        }
        #pragma unroll
        for (int j = 0; j < 4; j++) {
            int row = ldrow + j * 32;
            cp16(so + ASZ + swzB(row, ldseg), gb + (size_t)row * (CC * 2) + ldseg * 16);
        }
        CP_COMMIT();
    };

    load_stage(0, 0);
    load_stage(1, 1);

    uint32_t acc[4][4][2] = {};           // warp 64m x 32n, f16x2 acc
    const int mw = (wid >> 2) * 64;       // warp row: 0/64
    const int nw = (wid & 3) * 32;        // warp col: 0/32/64/96
    const int rowSel = (lane & 7) + ((lane >> 3) & 1) * 8;
    const int segHi  = (lane >> 4) & 1;

    uint32_t af[2][4][4], bf[2][2][4];
    auto ldsm_step = [&](uint32_t aBase, uint32_t bBase, int ks, int buf) {
        const int kseg = ks * 2 + segHi;
        #pragma unroll
        for (int mt = 0; mt < 4; mt++)
            ldsm4(af[buf][mt], aBase + swzB(mw + mt * 16 + rowSel, kseg));
        #pragma unroll
        for (int nb = 0; nb < 2; nb++)
            ldsm4(bf[buf][nb], bBase + swzB(nw + nb * 16 + rowSel, kseg));
    };
    auto mma_step = [&](int buf) {
        #pragma unroll
        for (int mt = 0; mt < 4; mt++) {
            #pragma unroll
            for (int nt = 0; nt < 4; nt++)
                mma_h(acc[mt][nt], af[buf][mt],
                      bf[buf][nt >> 1][nt & 1], bf[buf][nt >> 1][(nt & 1) + 2]);
        }
    };

    #pragma unroll
    for (int c = 0; c < NCHNK; c++) {
        if (c < NCHNK - 1) { CP_WAIT(1); } else { CP_WAIT(0); }
        __syncthreads();
        if (c + 2 < NCHNK) load_stage(c + 2, (c + 2) % 3);

        const uint32_t aBase = sb + (uint32_t)(c % 3) * STAGEB;
        const uint32_t bBase = aBase + ASZ;

        ldsm_step(aBase, bBase, 0, 0);
        #pragma unroll
        for (int ks = 0; ks < 4; ks++) {
            const int cur = ks & 1;
            if (ks < 3) ldsm_step(aBase, bBase, ks + 1, cur ^ 1);
            mma_step(cur);
        }
    }

    // ---- stage D through smem ----
    float* tile = reinterpret_cast<float*>(smem);
    __syncthreads();                       // stages dead; safe to reuse
    const int dr = lane >> 2;
    const int dc = (lane & 3) * 2;
    #pragma unroll
    for (int mt = 0; mt < 4; mt++) {
        #pragma unroll
        for (int nt = 0; nt < 4; nt++) {
            int r = mw + mt * 16 + dr;
            int c2 = nw + nt * 8 + dc;
            float2 lo = __half22float2(*reinterpret_cast<__half2*>(&acc[mt][nt][0]));
            float2 hi = __half22float2(*reinterpret_cast<__half2*>(&acc[mt][nt][1]));
            tile[r * TPITCH + c2]           = lo.x;
            tile[r * TPITCH + c2 + 1]       = lo.y;
            tile[(r + 8) * TPITCH + c2]     = hi.x;
            tile[(r + 8) * TPITCH + c2 + 1] = hi.y;
        }
    }
    __syncthreads();

    // ---- epilogue: BN + residual + RPReLU, coalesced over hw ----
    #pragma unroll 4
    for (int g = 0; g < 16; g++) {
        const int nl = wid + 8 * g;
        const int n = n0 + nl;
        const float al = alphaS[nl], be = betaS[nl];
        const float sl = slopeS[nl], sh = shiftS[nl], pb = pbiasS[nl];
        #pragma unroll
        for (int j = 0; j < 4; j++) {
            int ml = lane + 32 * j;
            int m = m0 + ml;
            int b = m / HWS;
            int hw = m - b * HWS;
            size_t gi = ((size_t)(b * CC + n)) * HWS + hw;
            float raw = tile[ml * TPITCH + nl];
            float sv = fmaf(al, raw, be) + x[gi];
            float t = sv - sh;
            out[gi] = ((t > 0.f) ? t : sl * t) + pb;
        }
    }
}

// ---------------- launch ----------------
extern "C" void kernel_launch(void* const* d_in, const int* in_sizes, int n_in,
                              void* d_out, int out_size) {
    const float* x   = (const float*)d_in[0];
    const float* rb  = (const float*)d_in[1];
    const float* W   = (const float*)d_in[2];
    const float* gam = (const float*)d_in[3];
    const float* bet = (const float*)d_in[4];
    const float* mea = (const float*)d_in[5];
    const float* var = (const float*)d_in[6];
    const float* slo = (const float*)d_in[7];
    const float* shi = (const float*)d_in[8];
    const float* pbi = (const float*)d_in[9];
    float* out = (float*)d_out;

    cudaFuncSetAttribute(gemm_kernel, cudaFuncAttributeMaxDynamicSharedMemorySize, SMTOTAL);

    prep_kernel<<<64, 256>>>(W, gam, bet, mea, var);
    binarize_kernel<<<dim3(13, 8, 64), 256>>>(x, rb);
    gemm_kernel<<<dim3(4, MTOT / MTILE), 256, SMTOTAL>>>(x, slo, shi, pbi, out);
}